// round 3
// baseline (speedup 1.0000x reference)
#include <cuda_runtime.h>

// out[i,j] = | prod_k cos((x[i,k]-y[j,k])/2) |
// Identity: cos((a-b)/2) = cos(a/2)cos(b/2) + sin(a/2)sin(b/2)
// Precompute per-row (cos,sin) of half-angles in smem, then the inner loop is
// pure FFMA: t = fma(sx, sy, cx*cy); prod *= t.

#define D   16
#define BM  64
#define BN  64
#define TM  4
#define TN  4
#define NTX 16
#define NTY 16

__global__ __launch_bounds__(NTX * NTY)
void qk_kernel(const float* __restrict__ x, const float* __restrict__ y,
               float* __restrict__ out, int n, int m) {
    // smem layout [k][row] so that at fixed k consecutive rows are consecutive
    // float2 -> conflict-free / broadcast LDS.64 in the main loop.
    __shared__ float2 sx[D][BM];  // (cos(x/2), sin(x/2)) for BM x-rows
    __shared__ float2 sy[D][BN];  // (cos(y/2), sin(y/2)) for BN y-rows

    const int tid = threadIdx.x;
    const int tx  = tid % NTX;          // j direction
    const int ty  = tid / NTX;          // i direction
    const int bi  = blockIdx.y * BM;    // tile row origin
    const int bj  = blockIdx.x * BN;    // tile col origin

    // ---- Precompute phase: fill sincos tiles (1024 entries per side) ----
    for (int idx = tid; idx < BM * D; idx += NTX * NTY) {
        int row = idx / D;
        int k   = idx % D;
        int gr  = bi + row;
        float v = (gr < n) ? x[gr * D + k] : 0.0f;
        float s, c;
        __sincosf(0.5f * v, &s, &c);
        sx[k][row] = make_float2(c, s);
    }
    for (int idx = tid; idx < BN * D; idx += NTX * NTY) {
        int row = idx / D;
        int k   = idx % D;
        int gr  = bj + row;
        float v = (gr < m) ? y[gr * D + k] : 0.0f;
        float s, c;
        __sincosf(0.5f * v, &s, &c);
        sy[k][row] = make_float2(c, s);
    }
    __syncthreads();

    // ---- Main phase: 4x4 register tile per thread, k fully unrolled ----
    float acc[TM][TN];
#pragma unroll
    for (int ii = 0; ii < TM; ii++)
#pragma unroll
        for (int jj = 0; jj < TN; jj++)
            acc[ii][jj] = 1.0f;

    const int i0 = ty * TM;
    const int j0 = tx * TN;

#pragma unroll
    for (int k = 0; k < D; k++) {
        float2 xa[TM], yb[TN];
#pragma unroll
        for (int ii = 0; ii < TM; ii++) xa[ii] = sx[k][i0 + ii];
#pragma unroll
        for (int jj = 0; jj < TN; jj++) yb[jj] = sy[k][j0 + jj];
#pragma unroll
        for (int ii = 0; ii < TM; ii++) {
#pragma unroll
            for (int jj = 0; jj < TN; jj++) {
                float t = fmaf(xa[ii].y, yb[jj].y, xa[ii].x * yb[jj].x);
                acc[ii][jj] *= t;
            }
        }
    }

    // ---- Store: float4 per row-fragment (m=2048, j aligned to 4) ----
#pragma unroll
    for (int ii = 0; ii < TM; ii++) {
        int gi = bi + i0 + ii;
        int gj = bj + j0;
        if (gi < n && gj + TN <= m) {
            float4 v;
            v.x = fabsf(acc[ii][0]);
            v.y = fabsf(acc[ii][1]);
            v.z = fabsf(acc[ii][2]);
            v.w = fabsf(acc[ii][3]);
            *reinterpret_cast<float4*>(&out[(long)gi * m + gj]) = v;
        } else if (gi < n) {
            for (int jj = 0; jj < TN; jj++)
                if (gj + jj < m) out[(long)gi * m + gj + jj] = fabsf(acc[ii][jj]);
        }
    }
}

extern "C" void kernel_launch(void* const* d_in, const int* in_sizes, int n_in,
                              void* d_out, int out_size) {
    const float* x = (const float*)d_in[0];
    const float* y = (const float*)d_in[1];
    float* out = (float*)d_out;
    int n = in_sizes[0] / D;
    int m = in_sizes[1] / D;

    dim3 block(NTX * NTY);
    dim3 grid((m + BN - 1) / BN, (n + BM - 1) / BM);
    qk_kernel<<<grid, block>>>(x, y, out, n, m);
}

// round 4
// speedup vs baseline: 1.3377x; 1.3377x over previous
#include <cuda_runtime.h>

// out[i,j] = | prod_k cos((x[i,k]-y[j,k])/2) |
//
// Identity per wire: cos((a-b)/2) = cos(a/2)cos(b/2) + sin(a/2)sin(b/2)
// Pair wires (2k, 2k+1):  t_2k * t_2k+1 = X . Y  (4-dim dot) where
//   X = (c0*c1, c0*s1, s0*c1, s0*s1) from (cos,sin) of the two half-angles.
// Per pair: 1 mul + 3 fma + 1 acc-mul = 5 FFMA-class ops per 2 wires.
//
// Tiling: 128x128 output tile per 256-thread block, 8x8 register tile per
// thread with STRIDED index assignment (i = ty + ii*16, j = tx + jj*16) so
// all smem loads are conflict-free LDS.128.

#define D    16
#define KP   8          // wire pairs
#define BM   128
#define BN   128
#define NT   256

__global__ __launch_bounds__(NT)
void qk_kernel(const float* __restrict__ x, const float* __restrict__ y,
               float* __restrict__ out, int n, int m) {
    __shared__ float4 sx4[KP][BM];   // per x-row, per pair: 4 trig combos
    __shared__ float4 sy4[KP][BN];

    const int tid = threadIdx.x;
    const int bi  = blockIdx.y * BM;
    const int bj  = blockIdx.x * BN;

    // ---- Fill phase: one thread per tile row (128 x-rows + 128 y-rows) ----
    {
        const int  r    = tid & 127;
        const bool isY  = (tid >= 128);
        const int  gr   = (isY ? bj : bi) + r;
        const int  lim  = isY ? m : n;
        const float* src = isY ? y : x;

        float v[D];
        if (gr < lim) {
            const float4* p = reinterpret_cast<const float4*>(src + (size_t)gr * D);
            float4 a = p[0], b = p[1], c = p[2], d = p[3];
            v[0]=a.x;  v[1]=a.y;  v[2]=a.z;  v[3]=a.w;
            v[4]=b.x;  v[5]=b.y;  v[6]=b.z;  v[7]=b.w;
            v[8]=c.x;  v[9]=c.y;  v[10]=c.z; v[11]=c.w;
            v[12]=d.x; v[13]=d.y; v[14]=d.z; v[15]=d.w;
        } else {
#pragma unroll
            for (int k = 0; k < D; k++) v[k] = 0.0f;
        }

        float4 (*dst)[BM] = isY ? sy4 : sx4;
#pragma unroll
        for (int kp = 0; kp < KP; kp++) {
            float s0, c0, s1, c1;
            __sincosf(0.5f * v[2*kp + 0], &s0, &c0);
            __sincosf(0.5f * v[2*kp + 1], &s1, &c1);
            dst[kp][r] = make_float4(c0*c1, c0*s1, s0*c1, s0*s1);
        }
    }
    __syncthreads();

    // ---- Main phase: 8x8 register tile, strided i/j for conflict-free LDS ----
    const int tx = tid & 15;    // j direction
    const int ty = tid >> 4;    // i direction

    float acc[8][8];
#pragma unroll
    for (int ii = 0; ii < 8; ii++)
#pragma unroll
        for (int jj = 0; jj < 8; jj++)
            acc[ii][jj] = 1.0f;

#pragma unroll 4
    for (int kp = 0; kp < KP; kp++) {
        float4 yb[8];
#pragma unroll
        for (int jj = 0; jj < 8; jj++) yb[jj] = sy4[kp][tx + jj*16];
#pragma unroll
        for (int ii = 0; ii < 8; ii++) {
            float4 xa = sx4[kp][ty + ii*16];
#pragma unroll
            for (int jj = 0; jj < 8; jj++) {
                float t = xa.x * yb[jj].x;
                t = fmaf(xa.y, yb[jj].y, t);
                t = fmaf(xa.z, yb[jj].z, t);
                t = fmaf(xa.w, yb[jj].w, t);
                acc[ii][jj] *= t;
            }
        }
    }

    // ---- Store: strided scalar stores (lanes coalesce into 64B runs) ----
    if (bi + BM <= n && bj + BN <= m) {
#pragma unroll
        for (int ii = 0; ii < 8; ii++) {
            float* row = out + (size_t)(bi + ty + ii*16) * m + (bj + tx);
#pragma unroll
            for (int jj = 0; jj < 8; jj++)
                row[jj*16] = fabsf(acc[ii][jj]);
        }
    } else {
#pragma unroll
        for (int ii = 0; ii < 8; ii++) {
            int gi = bi + ty + ii*16;
            if (gi >= n) continue;
#pragma unroll
            for (int jj = 0; jj < 8; jj++) {
                int gj = bj + tx + jj*16;
                if (gj < m) out[(size_t)gi * m + gj] = fabsf(acc[ii][jj]);
            }
        }
    }
}

extern "C" void kernel_launch(void* const* d_in, const int* in_sizes, int n_in,
                              void* d_out, int out_size) {
    const float* x = (const float*)d_in[0];
    const float* y = (const float*)d_in[1];
    float* out = (float*)d_out;
    int n = in_sizes[0] / D;
    int m = in_sizes[1] / D;

    dim3 block(NT);
    dim3 grid((m + BN - 1) / BN, (n + BM - 1) / BM);
    qk_kernel<<<grid, block>>>(x, y, out, n, m);
}

// round 5
// speedup vs baseline: 1.5138x; 1.1316x over previous
#include <cuda_runtime.h>
#include <cstdint>

// out[i,j] = | prod_k cos((x[i,k]-y[j,k])/2) |
//
// Per wire: cos((a-b)/2) = cos(a/2)cos(b/2) + sin(a/2)sin(b/2)
// Pair wires (2k,2k+1): t_2k*t_2k+1 = X.Y (4-dim dot),
//   X = (c0c1, c0s1, s0c1, s0s1), same form for Y.
//
// Inner loop uses Blackwell packed f32x2 FMA: each instruction advances TWO
// adjacent output columns. y smem is SoA per component (LDS.64 -> packed j
// pair); x smem is pre-duplicated {v,v} (LDS.64 -> broadcast operand).

#define D    16
#define KP   8
#define BM   128
#define BN   128
#define NT   256

#define FMA_X2(d, a, b, c) \
    asm("fma.rn.f32x2 %0, %1, %2, %3;" : "=l"(d) : "l"(a), "l"(b), "l"(c))
#define MUL_X2(d, a, b) \
    asm("mul.rn.f32x2 %0, %1, %2;" : "=l"(d) : "l"(a), "l"(b))

__global__ __launch_bounds__(NT)
void qk_kernel(const float* __restrict__ x, const float* __restrict__ y,
               float* __restrict__ out, int n, int m) {
    // x side: 4 trig components per pair, each value DUPLICATED into a float2
    // so an LDS.64 yields a packed broadcast operand.
    __shared__ float2 sxd[KP][4][BM];          // 32 KB
    // y side: SoA per component; adjacent j values adjacent in memory.
    __shared__ float  sy[KP][4][BN];           // 16 KB

    const int tid = threadIdx.x;
    const int bi  = blockIdx.y * BM;
    const int bj  = blockIdx.x * BN;

    // ---- Fill: thread r<128 handles x-row r; r>=128 handles y-row r-128 ----
    {
        const int  r    = tid & 127;
        const bool isY  = (tid >= 128);
        const int  gr   = (isY ? bj : bi) + r;
        const int  lim  = isY ? m : n;
        const float* src = isY ? y : x;

        float v[D];
        if (gr < lim) {
            const float4* p = reinterpret_cast<const float4*>(src + (size_t)gr * D);
            float4 a = p[0], b = p[1], c = p[2], d = p[3];
            v[0]=a.x;  v[1]=a.y;  v[2]=a.z;  v[3]=a.w;
            v[4]=b.x;  v[5]=b.y;  v[6]=b.z;  v[7]=b.w;
            v[8]=c.x;  v[9]=c.y;  v[10]=c.z; v[11]=c.w;
            v[12]=d.x; v[13]=d.y; v[14]=d.z; v[15]=d.w;
        } else {
#pragma unroll
            for (int k = 0; k < D; k++) v[k] = 0.0f;  // cos(0)=1 padding
        }

#pragma unroll
        for (int kp = 0; kp < KP; kp++) {
            float s0, c0, s1, c1;
            __sincosf(0.5f * v[2*kp + 0], &s0, &c0);
            __sincosf(0.5f * v[2*kp + 1], &s1, &c1);
            float w0 = c0*c1, w1 = c0*s1, w2 = s0*c1, w3 = s0*s1;
            if (isY) {
                sy[kp][0][r] = w0; sy[kp][1][r] = w1;
                sy[kp][2][r] = w2; sy[kp][3][r] = w3;
            } else {
                sxd[kp][0][r] = make_float2(w0, w0);
                sxd[kp][1][r] = make_float2(w1, w1);
                sxd[kp][2][r] = make_float2(w2, w2);
                sxd[kp][3][r] = make_float2(w3, w3);
            }
        }
    }
    __syncthreads();

    // ---- Main: 8 rows x 4 packed col-pairs per thread ----
    // i  = bi + ty + 16*ii          (ii = 0..7)
    // j2 = bj + 2*tx + 32*jj2       (jj2 = 0..3, each covers cols j2, j2+1)
    const int tx = tid & 15;
    const int ty = tid >> 4;

    const uint64_t ONE2 = 0x3F8000003F800000ULL;  // (1.0f, 1.0f)
    uint64_t acc[8][4];
#pragma unroll
    for (int ii = 0; ii < 8; ii++)
#pragma unroll
        for (int jj2 = 0; jj2 < 4; jj2++)
            acc[ii][jj2] = ONE2;

#pragma unroll 2
    for (int kp = 0; kp < KP; kp++) {
        uint64_t yb[4][4];   // [component][jj2]
#pragma unroll
        for (int jj2 = 0; jj2 < 4; jj2++) {
#pragma unroll
            for (int c = 0; c < 4; c++)
                yb[c][jj2] = reinterpret_cast<const uint64_t*>(sy[kp][c])[tx + 16*jj2];
        }
#pragma unroll
        for (int ii = 0; ii < 8; ii++) {
            const int row = ty + 16*ii;
            uint64_t x0 = *reinterpret_cast<const uint64_t*>(&sxd[kp][0][row]);
            uint64_t x1 = *reinterpret_cast<const uint64_t*>(&sxd[kp][1][row]);
            uint64_t x2 = *reinterpret_cast<const uint64_t*>(&sxd[kp][2][row]);
            uint64_t x3 = *reinterpret_cast<const uint64_t*>(&sxd[kp][3][row]);
#pragma unroll
            for (int jj2 = 0; jj2 < 4; jj2++) {
                uint64_t t;
                MUL_X2(t, x0, yb[0][jj2]);
                FMA_X2(t, x1, yb[1][jj2], t);
                FMA_X2(t, x2, yb[2][jj2], t);
                FMA_X2(t, x3, yb[3][jj2], t);
                MUL_X2(acc[ii][jj2], acc[ii][jj2], t);
            }
        }
    }

    // ---- Store: packed abs (64-bit AND) + STG.64, cols adjacent ----
    const uint64_t ABS2 = 0x7FFFFFFF7FFFFFFFULL;
    if (bi + BM <= n && bj + BN <= m) {
#pragma unroll
        for (int ii = 0; ii < 8; ii++) {
            float* row = out + (size_t)(bi + ty + 16*ii) * m + (bj + 2*tx);
#pragma unroll
            for (int jj2 = 0; jj2 < 4; jj2++)
                *reinterpret_cast<uint64_t*>(row + 32*jj2) = acc[ii][jj2] & ABS2;
        }
    } else {
#pragma unroll
        for (int ii = 0; ii < 8; ii++) {
            int gi = bi + ty + 16*ii;
            if (gi >= n) continue;
#pragma unroll
            for (int jj2 = 0; jj2 < 4; jj2++) {
                uint64_t a = acc[ii][jj2] & ABS2;
                float lo = __uint_as_float((uint32_t)a);
                float hi = __uint_as_float((uint32_t)(a >> 32));
                int gj = bj + 2*tx + 32*jj2;
                if (gj     < m) out[(size_t)gi * m + gj]     = lo;
                if (gj + 1 < m) out[(size_t)gi * m + gj + 1] = hi;
            }
        }
    }
}

extern "C" void kernel_launch(void* const* d_in, const int* in_sizes, int n_in,
                              void* d_out, int out_size) {
    const float* x = (const float*)d_in[0];
    const float* y = (const float*)d_in[1];
    float* out = (float*)d_out;
    int n = in_sizes[0] / D;
    int m = in_sizes[1] / D;

    dim3 block(NT);
    dim3 grid((m + BN - 1) / BN, (n + BM - 1) / BM);
    qk_kernel<<<grid, block>>>(x, y, out, n, m);
}

// round 6
// speedup vs baseline: 1.5400x; 1.0173x over previous
#include <cuda_runtime.h>
#include <cstdint>

// out[i,j] = | prod_k cos((x[i,k]-y[j,k])/2) |
//
// Per wire: cos((a-b)/2) = cos(a/2)cos(b/2) + sin(a/2)sin(b/2)
// Pair wires (2k,2k+1): t_2k*t_2k+1 = X.Y (4-dim dot),
//   X = (c0c1, c0s1, s0c1, s0s1), same for Y.
//
// Packed f32x2 FMA advances two adjacent output columns per instruction.
// x smem: one float4 per (kp,row) -> LDS.128 broadcast, duplicated into
// packed operands in registers (mov.b64 {v,v}, ALU pipe).
// y smem: SoA per component -> LDS.64 gives a natural packed column pair.

#define D    16
#define KP   8
#define BM   128
#define BN   64
#define NT   256

#define FMA_X2(d, a, b, c) \
    asm("fma.rn.f32x2 %0, %1, %2, %3;" : "=l"(d) : "l"(a), "l"(b), "l"(c))
#define MUL_X2(d, a, b) \
    asm("mul.rn.f32x2 %0, %1, %2;" : "=l"(d) : "l"(a), "l"(b))
#define DUP_X2(d, v) \
    asm("mov.b64 %0, {%1, %1};" : "=l"(d) : "r"(v))

__global__ __launch_bounds__(NT, 3)
void qk_kernel(const float* __restrict__ x, const float* __restrict__ y,
               float* __restrict__ out, int n, int m) {
    __shared__ float4 sx4[KP][BM];      // 16 KB: (w0,w1,w2,w3) per x-row
    __shared__ float  sy[KP][4][BN];    //  8 KB: SoA per component

    const int tid = threadIdx.x;
    const int bi  = blockIdx.y * BM;
    const int bj  = blockIdx.x * BN;

    // ---- Fill: threads 0..127 -> x rows, 128..191 -> y rows ----
    if (tid < BM + BN) {
        const bool isY  = (tid >= BM);
        const int  r    = isY ? (tid - BM) : tid;
        const int  gr   = (isY ? bj : bi) + r;
        const int  lim  = isY ? m : n;
        const float* src = isY ? y : x;

        float v[D];
        if (gr < lim) {
            const float4* p = reinterpret_cast<const float4*>(src + (size_t)gr * D);
            float4 a = p[0], b = p[1], c = p[2], d = p[3];
            v[0]=a.x;  v[1]=a.y;  v[2]=a.z;  v[3]=a.w;
            v[4]=b.x;  v[5]=b.y;  v[6]=b.z;  v[7]=b.w;
            v[8]=c.x;  v[9]=c.y;  v[10]=c.z; v[11]=c.w;
            v[12]=d.x; v[13]=d.y; v[14]=d.z; v[15]=d.w;
        } else {
#pragma unroll
            for (int k = 0; k < D; k++) v[k] = 0.0f;  // cos(0)=1 padding
        }

#pragma unroll
        for (int kp = 0; kp < KP; kp++) {
            float s0, c0, s1, c1;
            __sincosf(0.5f * v[2*kp + 0], &s0, &c0);
            __sincosf(0.5f * v[2*kp + 1], &s1, &c1);
            float w0 = c0*c1, w1 = c0*s1, w2 = s0*c1, w3 = s0*s1;
            if (isY) {
                sy[kp][0][r] = w0; sy[kp][1][r] = w1;
                sy[kp][2][r] = w2; sy[kp][3][r] = w3;
            } else {
                sx4[kp][r] = make_float4(w0, w1, w2, w3);
            }
        }
    }
    __syncthreads();

    // ---- Main: 8 rows x 2 packed col-pairs per thread ----
    // i  = bi + ty + 16*ii   (ii = 0..7)
    // j  = bj + 2*tx + 32*jj2 (+0/+1 packed; jj2 = 0..1)
    const int tx = tid & 15;
    const int ty = tid >> 4;

    const uint64_t ONE2 = 0x3F8000003F800000ULL;
    uint64_t acc[8][2];
#pragma unroll
    for (int ii = 0; ii < 8; ii++) {
        acc[ii][0] = ONE2;
        acc[ii][1] = ONE2;
    }

#pragma unroll 2
    for (int kp = 0; kp < KP; kp++) {
        uint64_t yb[4][2];
#pragma unroll
        for (int jj2 = 0; jj2 < 2; jj2++)
#pragma unroll
            for (int c = 0; c < 4; c++)
                yb[c][jj2] = reinterpret_cast<const uint64_t*>(sy[kp][c])[tx + 16*jj2];

#pragma unroll
        for (int ii = 0; ii < 8; ii++) {
            float4 xa = sx4[kp][ty + 16*ii];
            uint64_t x0, x1, x2, x3;
            DUP_X2(x0, __float_as_uint(xa.x));
            DUP_X2(x1, __float_as_uint(xa.y));
            DUP_X2(x2, __float_as_uint(xa.z));
            DUP_X2(x3, __float_as_uint(xa.w));
#pragma unroll
            for (int jj2 = 0; jj2 < 2; jj2++) {
                uint64_t t;
                MUL_X2(t, x0, yb[0][jj2]);
                FMA_X2(t, x1, yb[1][jj2], t);
                FMA_X2(t, x2, yb[2][jj2], t);
                FMA_X2(t, x3, yb[3][jj2], t);
                MUL_X2(acc[ii][jj2], acc[ii][jj2], t);
            }
        }
    }

    // ---- Store: packed abs (64-bit AND) + STG.64 ----
    const uint64_t ABS2 = 0x7FFFFFFF7FFFFFFFULL;
    if (bi + BM <= n && bj + BN <= m) {
#pragma unroll
        for (int ii = 0; ii < 8; ii++) {
            float* row = out + (size_t)(bi + ty + 16*ii) * m + (bj + 2*tx);
            *reinterpret_cast<uint64_t*>(row)      = acc[ii][0] & ABS2;
            *reinterpret_cast<uint64_t*>(row + 32) = acc[ii][1] & ABS2;
        }
    } else {
#pragma unroll
        for (int ii = 0; ii < 8; ii++) {
            int gi = bi + ty + 16*ii;
            if (gi >= n) continue;
#pragma unroll
            for (int jj2 = 0; jj2 < 2; jj2++) {
                uint64_t a = acc[ii][jj2] & ABS2;
                int gj = bj + 2*tx + 32*jj2;
                if (gj     < m) out[(size_t)gi * m + gj]     = __uint_as_float((uint32_t)a);
                if (gj + 1 < m) out[(size_t)gi * m + gj + 1] = __uint_as_float((uint32_t)(a >> 32));
            }
        }
    }
}

extern "C" void kernel_launch(void* const* d_in, const int* in_sizes, int n_in,
                              void* d_out, int out_size) {
    const float* x = (const float*)d_in[0];
    const float* y = (const float*)d_in[1];
    float* out = (float*)d_out;
    int n = in_sizes[0] / D;
    int m = in_sizes[1] / D;

    dim3 block(NT);
    dim3 grid((m + BN - 1) / BN, (n + BM - 1) / BM);
    qk_kernel<<<grid, block>>>(x, y, out, n, m);
}